// round 3
// baseline (speedup 1.0000x reference)
#include <cuda_runtime.h>

#define FULL_MASK 0xffffffffu

// ---------- packed f32x2 + fast-math helpers ----------
__device__ __forceinline__ float2 ffma2(float2 a, float2 b, float2 c) {
    unsigned long long au = *reinterpret_cast<unsigned long long*>(&a);
    unsigned long long bu = *reinterpret_cast<unsigned long long*>(&b);
    unsigned long long cu = *reinterpret_cast<unsigned long long*>(&c);
    unsigned long long du;
    asm("fma.rn.f32x2 %0, %1, %2, %3;" : "=l"(du) : "l"(au), "l"(bu), "l"(cu));
    return *reinterpret_cast<float2*>(&du);
}
__device__ __forceinline__ float2 fadd2(float2 a, float2 b) {
    unsigned long long au = *reinterpret_cast<unsigned long long*>(&a);
    unsigned long long bu = *reinterpret_cast<unsigned long long*>(&b);
    unsigned long long du;
    asm("add.rn.f32x2 %0, %1, %2;" : "=l"(du) : "l"(au), "l"(bu));
    return *reinterpret_cast<float2*>(&du);
}
__device__ __forceinline__ float ex2a(float x) {
    float r; asm("ex2.approx.f32 %0, %1;" : "=f"(r) : "f"(x)); return r;
}
__device__ __forceinline__ float rcpa(float x) {
    float r; asm("rcp.approx.f32 %0, %1;" : "=f"(r) : "f"(x)); return r;
}

// H=32, 4H=128 gate rows, I=1, T=512, B=8192.
//
// CTA = 128 threads, NB = 8 batches per CTA (grid = 1024).
// GATE phase: thread t owns gate rows m0 = t&63 and m1 = m0+64; the two
//   64-thread halves (s = t>>6) process a batch PAIR per pass, 4 passes/step.
//   Dot products are k-pair packed fma.rn.f32x2 against h broadcast from smem.
// ACT phase: thread t owns hidden cells (batch=w, j) and (batch=w+4, j),
//   w = warp id, j = lane. c stays in registers; h goes through smem.
// Two __syncthreads per step decouple phases; 5 CTAs/SM give the SMSPs
// ~5 independent warps to hide each CTA's activation/barrier tail.
//
// Activation prescales folded into weights/biases:
//   sigmoid(a) = rcp(1 + ex2(P_SIG*a)),      P_SIG  = -log2(e)
//   tanh(a)    = 1 - 2*rcp(1 + ex2(P_TANH*a)), P_TANH = 2*log2(e)
// Gate rows 0..63 are i,f (sigmoid); 64..95 g (tanh); 96..127 o (sigmoid).

__global__ void __launch_bounds__(128, 5) lstm_h32_kernel(
    const float* __restrict__ x,      // [B, 512]
    const float* __restrict__ W_ih,   // [128]
    const float* __restrict__ W_hh,   // [128, 32]
    const float* __restrict__ b_ih,   // [128]
    const float* __restrict__ b_hh,   // [128]
    const float* __restrict__ W_lin,  // [32]
    const float* __restrict__ b_lin,  // [1]
    float* __restrict__ out)          // [B]
{
    __shared__ float swhh[128 * 34];          // prologue staging (stride 34)
    __shared__ __align__(16) float hsm[8][32]; // h[batch][unit]
    __shared__ float agm[8][128];              // gate preacts a[batch][row]
    __shared__ float xsm[8][32];               // x chunk [batch][step-in-chunk]

    const int tid = threadIdx.x;

    for (int i = tid; i < 128 * 32; i += 128)
        swhh[(i >> 5) * 34 + (i & 31)] = W_hh[i];
    __syncthreads();

    const float P_SIG  = -1.4426950408889634f;
    const float P_TANH =  2.8853900817779268f;

    // ---- gate-phase identity ----
    const int s  = tid >> 6;        // batch-sub within pair
    const int m0 = tid & 63;        // rows m0 (i/f) and m1 (g/o)
    const int m1 = m0 + 64;
    const float PS1 = (m1 < 96) ? P_TANH : P_SIG;

    float2 wv0[16], wv1[16];
    #pragma unroll
    for (int q = 0; q < 16; ++q) {
        float2 t0 = *reinterpret_cast<const float2*>(&swhh[m0 * 34 + 2 * q]);
        float2 t1 = *reinterpret_cast<const float2*>(&swhh[m1 * 34 + 2 * q]);
        wv0[q] = make_float2(P_SIG * t0.x, P_SIG * t0.y);
        wv1[q] = make_float2(PS1   * t1.x, PS1   * t1.y);
    }
    const float pwih0 = P_SIG * W_ih[m0];
    const float pwih1 = PS1   * W_ih[m1];
    const float pb0   = P_SIG * (b_ih[m0] + b_hh[m0]);
    const float pb1   = PS1   * (b_ih[m1] + b_hh[m1]);

    // ---- act-phase identity ----
    const int w = tid >> 5;         // warp id -> batch w and w+4
    const int j = tid & 31;         // hidden unit
    float c0 = 0.0f, c1 = 0.0f;
    float h0r = 0.0f, h1r = 0.0f;

    // zero h
    for (int i = tid; i < 8 * 32; i += 128)
        (&hsm[0][0])[i] = 0.0f;

    // ---- x double-buffered in registers, 32 steps / chunk ----
    const int b0 = blockIdx.x * 8;
    const int bx = tid >> 4;                 // batch for x staging
    const int i2 = (tid & 15) * 2;           // 2 consecutive steps
    const float* px = x + (size_t)(b0 + bx) * 512 + i2;
    float2 rxv = *reinterpret_cast<const float2*>(px);

    for (int ch = 0; ch < 16; ++ch) {
        *reinterpret_cast<float2*>(&xsm[bx][i2]) = rxv;
        __syncthreads();                      // xsm + h ready
        if (ch < 15)
            rxv = *reinterpret_cast<const float2*>(px + 32 * (ch + 1));

        #pragma unroll 1
        for (int tl = 0; tl < 32; ++tl) {
            // ---------------- gate phase ----------------
            #pragma unroll 1
            for (int p = 0; p < 4; ++p) {
                const int b = 2 * p + s;
                const float xtb = xsm[b][tl];
                float2 a0a = make_float2(fmaf(xtb, pwih0, pb0), 0.0f);
                float2 a1a = make_float2(fmaf(xtb, pwih1, pb1), 0.0f);
                float2 a0b = make_float2(0.0f, 0.0f);
                float2 a1b = make_float2(0.0f, 0.0f);
                const float4* hb = reinterpret_cast<const float4*>(&hsm[b][0]);
                #pragma unroll
                for (int q = 0; q < 8; ++q) {
                    const float4 hv = hb[q];          // broadcast LDS.128
                    const float2 hA = make_float2(hv.x, hv.y);
                    const float2 hB = make_float2(hv.z, hv.w);
                    a0a = ffma2(hA, wv0[2 * q    ], a0a);
                    a0b = ffma2(hB, wv0[2 * q + 1], a0b);
                    a1a = ffma2(hA, wv1[2 * q    ], a1a);
                    a1b = ffma2(hB, wv1[2 * q + 1], a1b);
                }
                const float2 s0 = fadd2(a0a, a0b);
                const float2 s1 = fadd2(a1a, a1b);
                agm[b][m0] = s0.x + s0.y;
                agm[b][m1] = s1.x + s1.y;
            }
            __syncthreads();                  // gate preacts ready

            // ---------------- act phase ----------------
            {
                const float ai = agm[w][j];
                const float af = agm[w][j + 32];
                const float ag = agm[w][j + 64];
                const float ao = agm[w][j + 96];
                const float si = rcpa(1.0f + ex2a(ai));
                const float sf = rcpa(1.0f + ex2a(af));
                const float tg = fmaf(-2.0f, rcpa(1.0f + ex2a(ag)), 1.0f);
                const float so = rcpa(1.0f + ex2a(ao));
                c0 = fmaf(sf, c0, si * tg);
                const float tc = fmaf(-2.0f, rcpa(1.0f + ex2a(c0 * P_TANH)), 1.0f);
                h0r = so * tc;
                hsm[w][j] = h0r;
            }
            {
                const int b = w + 4;
                const float ai = agm[b][j];
                const float af = agm[b][j + 32];
                const float ag = agm[b][j + 64];
                const float ao = agm[b][j + 96];
                const float si = rcpa(1.0f + ex2a(ai));
                const float sf = rcpa(1.0f + ex2a(af));
                const float tg = fmaf(-2.0f, rcpa(1.0f + ex2a(ag)), 1.0f);
                const float so = rcpa(1.0f + ex2a(ao));
                c1 = fmaf(sf, c1, si * tg);
                const float tc = fmaf(-2.0f, rcpa(1.0f + ex2a(c1 * P_TANH)), 1.0f);
                h1r = so * tc;
                hsm[b][j] = h1r;
            }
            __syncthreads();                  // h published for next step
        }
    }

    // ---- epilogue: out[b] = dot(h[b], W_lin) + b_lin ----
    const float wl = W_lin[j];
    float v = h0r * wl;
    #pragma unroll
    for (int off = 16; off; off >>= 1)
        v += __shfl_xor_sync(FULL_MASK, v, off);
    if (j == 0) out[b0 + w] = v + b_lin[0];

    v = h1r * wl;
    #pragma unroll
    for (int off = 16; off; off >>= 1)
        v += __shfl_xor_sync(FULL_MASK, v, off);
    if (j == 0) out[b0 + w + 4] = v + b_lin[0];
}

extern "C" void kernel_launch(void* const* d_in, const int* in_sizes, int n_in,
                              void* d_out, int out_size) {
    const float* x     = (const float*)d_in[0];
    const float* W_ih  = (const float*)d_in[1];
    const float* W_hh  = (const float*)d_in[2];
    const float* b_ih  = (const float*)d_in[3];
    const float* b_hh  = (const float*)d_in[4];
    const float* W_lin = (const float*)d_in[5];
    const float* b_lin = (const float*)d_in[6];
    float* out = (float*)d_out;

    // 8192 batches / 8 per CTA = 1024 CTAs of 128 threads.
    lstm_h32_kernel<<<1024, 128>>>(x, W_ih, W_hh, b_ih, b_hh, W_lin, b_lin, out);
}